// round 12
// baseline (speedup 1.0000x reference)
#include <cuda_runtime.h>
#include <cuda_fp16.h>
#include <cstdint>

#define T  1024
#define HD 2048
#define ID 4096
#define E  8

#define APITCH 40   // fp16 elems; 80B row pitch (conflict-free for ldmatrix)
#define BPITCH 72   // fp16 elems; 144B row pitch
#define NK1 (HD / 32)
#define NK2 (ID / 32)

// double-buffer smem layout (bytes)
#define GU_A   0
#define GU_B0  10240
#define GU_B1  14848
#define GU_SS  19456
#define GU_BYTES (2 * GU_SS)

#define DN_A   0
#define DN_B   10240
#define DN_SS  14848
#define DN_BYTES (2 * DN_SS)

// ---- scratch ----
__device__ __half g_hs[(size_t)T * ID];
__device__ __half g_hr[(size_t)E * 1024 * ID];
__device__ int   g_expert[T];
__device__ float g_score[T];
__device__ int   g_perm[T];
__device__ int   g_offsets[E + 1];

// ---- helpers ----
__device__ __forceinline__ uint32_t smem_u32(const void* p) {
    uint32_t a;
    asm("{ .reg .u64 t; cvta.to.shared.u64 t, %1; cvt.u32.u64 %0, t; }" : "=r"(a) : "l"(p));
    return a;
}
__device__ __forceinline__ void ldsm4(uint32_t* r, uint32_t a) {
    asm volatile("ldmatrix.sync.aligned.m8n8.x4.shared.b16 {%0,%1,%2,%3}, [%4];"
                 : "=r"(r[0]), "=r"(r[1]), "=r"(r[2]), "=r"(r[3]) : "r"(a));
}
__device__ __forceinline__ void ldsm4t(uint32_t* r, uint32_t a) {
    asm volatile("ldmatrix.sync.aligned.m8n8.x4.trans.shared.b16 {%0,%1,%2,%3}, [%4];"
                 : "=r"(r[0]), "=r"(r[1]), "=r"(r[2]), "=r"(r[3]) : "r"(a));
}
__device__ __forceinline__ void mma_f16(float* c, const uint32_t* a, const uint32_t* b) {
    asm volatile("mma.sync.aligned.m16n8k16.row.col.f32.f16.f16.f32 "
                 "{%0,%1,%2,%3}, {%4,%5,%6,%7}, {%8,%9}, {%0,%1,%2,%3};"
                 : "+f"(c[0]), "+f"(c[1]), "+f"(c[2]), "+f"(c[3])
                 : "r"(a[0]), "r"(a[1]), "r"(a[2]), "r"(a[3]), "r"(b[0]), "r"(b[1]));
}
__device__ __forceinline__ uint32_t pack2(__half a, __half b) {
    __half2 t = __halves2half2(a, b);
    return *(uint32_t*)&t;
}
// 8 fp32 -> 8 fp16 with scale folded (sc=1 is exact identity of rn(v))
__device__ __forceinline__ uint4 cvtpack8(float4 v0, float4 v1, float sc) {
    return make_uint4(
        pack2(__float2half_rn(v0.x * sc), __float2half_rn(v0.y * sc)),
        pack2(__float2half_rn(v0.z * sc), __float2half_rn(v0.w * sc)),
        pack2(__float2half_rn(v1.x * sc), __float2half_rn(v1.y * sc)),
        pack2(__float2half_rn(v1.z * sc), __float2half_rn(v1.w * sc)));
}

// ============================================================================
__global__ void router_kernel(const float* __restrict__ x, const float* __restrict__ wr) {
    int warp = (blockIdx.x * blockDim.x + threadIdx.x) >> 5;
    int lane = threadIdx.x & 31;
    if (warp >= T) return;
    const float* xr = x + (size_t)warp * HD;
    float acc[E];
#pragma unroll
    for (int e = 0; e < E; e++) acc[e] = 0.f;
    for (int h = lane; h < HD; h += 32) {
        float xv = xr[h];
        const float* w = wr + (size_t)h * E;
#pragma unroll
        for (int e = 0; e < E; e++) acc[e] += xv * w[e];
    }
#pragma unroll
    for (int e = 0; e < E; e++) {
#pragma unroll
        for (int o = 16; o; o >>= 1) acc[e] += __shfl_xor_sync(0xffffffffu, acc[e], o);
    }
    if (lane == 0) {
        int best = 0; float bv = acc[0];
#pragma unroll
        for (int e = 1; e < E; e++) if (acc[e] > bv) { bv = acc[e]; best = e; }
        g_expert[warp] = best;
        g_score[warp]  = 1.f / (1.f + __expf(-bv));
    }
}

__global__ void perm_kernel() {
    __shared__ int cnt[E], off[E + 1], cur[E];
    int t = threadIdx.x;
    if (t < E) cnt[t] = 0;
    __syncthreads();
    int e = g_expert[t];
    atomicAdd(&cnt[e], 1);
    __syncthreads();
    if (t == 0) {
        off[0] = 0;
        for (int i = 0; i < E; i++) off[i + 1] = off[i] + cnt[i];
    }
    __syncthreads();
    if (t < E) cur[t] = off[t];
    __syncthreads();
    int pos = atomicAdd(&cur[e], 1);
    g_perm[pos] = t;
    if (t <= E) g_offsets[t] = off[t];
}

// ============================================================================
// GEMM1 (single launch): z=0 shared path, z=1..E routed expert z-1.
// h = silu(A@Wg)*(A@Wu); A = sc * x[tok] converted fp32->fp16 in staging.
// BM=128, BN=64, BK=32; 8 warps (4m x 2n), warp tile 32x32; double-buffered.
// ============================================================================
__global__ __launch_bounds__(256)
void gateup_kernel(const float* __restrict__ Wgs, const float* __restrict__ Wus,
                   const float* __restrict__ Wge, const float* __restrict__ Wue,
                   const float* __restrict__ X) {
    extern __shared__ char smem[];
    __shared__ int   s_tok[128];
    __shared__ float s_scl[128];

    int tid = threadIdx.x, wid = tid >> 5, lane = tid & 31;
    int z = blockIdx.z;

    int cnt, obase; size_t hrow0;
    const float *wg, *wu;
    __half* oh;
    if (z > 0) {
        int e = z - 1;
        obase = g_offsets[e]; cnt = g_offsets[e + 1] - obase;
        wg = Wge + (size_t)e * HD * ID; wu = Wue + (size_t)e * HD * ID;
        oh = g_hr; hrow0 = (size_t)e * 1024;
    } else {
        obase = 0; cnt = T; wg = Wgs; wu = Wus;
        oh = g_hs; hrow0 = 0;
    }
    int m0 = blockIdx.x * 128;
    if (m0 >= cnt) return;
    int n0 = blockIdx.y * 64;

    if (tid < 128) {
        int gr = m0 + tid;
        int tok = 0; float sc = 0.f;
        if (gr < cnt) {
            if (z > 0) { tok = g_perm[obase + gr]; sc = g_score[tok]; }
            else       { tok = gr;                 sc = 1.f; }
        }
        s_tok[tid] = tok; s_scl[tid] = sc;
    }
    __syncthreads();

    int sa_row = tid >> 1, sa_col = (tid & 1) * 16;
    float a_sc = s_scl[sa_row];
    const float* pX = X + (size_t)s_tok[sa_row] * HD + sa_col;
    int sb_k = tid >> 3, sb_j = (tid & 7) * 8;
    const float* pG = wg + (size_t)sb_k * ID + n0 + sb_j;
    const float* pU = wu + (size_t)sb_k * ID + n0 + sb_j;
    int a_boff = (sa_row * APITCH + sa_col) * 2;
    int b_boff = (sb_k * BPITCH + sb_j) * 2;

    int wm = (wid >> 1) * 32, wn = (wid & 1) * 32;
    uint32_t sbase = smem_u32(smem);
    int a_lr = lane & 15, a_lc = (lane >> 4) * 8;
    int b_lk = (lane & 7) + (lane >> 4) * 8, b_ln = ((lane >> 3) & 1) * 8;

    float accg[2][4][4] = {}, accu[2][4][4] = {};

    uint4 a_c0, a_c1, b_g, b_u;
#define GU_LDG(it) { \
    const float* px = pX + (it) * 32; \
    float4 t0 = *(const float4*)px,       t1 = *(const float4*)(px + 4); \
    float4 t2 = *(const float4*)(px + 8), t3 = *(const float4*)(px + 12); \
    a_c0 = cvtpack8(t0, t1, a_sc); a_c1 = cvtpack8(t2, t3, a_sc); \
    const float* pg = pG + (size_t)(it) * 32 * ID; \
    b_g = cvtpack8(*(const float4*)pg, *(const float4*)(pg + 4), 1.f); \
    const float* pu = pU + (size_t)(it) * 32 * ID; \
    b_u = cvtpack8(*(const float4*)pu, *(const float4*)(pu + 4), 1.f); }
#define GU_STS(st) { \
    char* base = smem + (st) * GU_SS; \
    *(uint4*)(base + GU_A + a_boff) = a_c0; \
    *(uint4*)(base + GU_A + a_boff + 16) = a_c1; \
    *(uint4*)(base + GU_B0 + b_boff) = b_g; \
    *(uint4*)(base + GU_B1 + b_boff) = b_u; }

    GU_LDG(0);
    GU_STS(0);
    GU_LDG(1);
    __syncthreads();

    int st = 0;
    for (int it = 0; it < NK1; it++) {
        if (it + 1 < NK1) {
            GU_STS(st ^ 1);
            if (it + 2 < NK1) GU_LDG(it + 2);
        }
        uint32_t sb = sbase + st * GU_SS;
#pragma unroll
        for (int kk = 0; kk < 32; kk += 16) {
            uint32_t ah[2][4];
#pragma unroll
            for (int mi = 0; mi < 2; mi++) {
                uint32_t ao = (uint32_t)((wm + mi * 16 + a_lr) * APITCH + kk + a_lc) * 2;
                ldsm4(ah[mi], sb + GU_A + ao);
            }
#pragma unroll
            for (int mat = 0; mat < 2; mat++) {
                uint32_t bh[4][2], r[4];
#pragma unroll
                for (int g2 = 0; g2 < 2; g2++) {
                    uint32_t bo = (uint32_t)((kk + b_lk) * BPITCH + wn + g2 * 16 + b_ln) * 2;
                    ldsm4t(r, sb + (mat ? GU_B1 : GU_B0) + bo);
                    bh[2*g2][0] = r[0]; bh[2*g2][1] = r[2];
                    bh[2*g2+1][0] = r[1]; bh[2*g2+1][1] = r[3];
                }
                float (*acc)[4][4] = mat ? accu : accg;
#pragma unroll
                for (int mi = 0; mi < 2; mi++)
#pragma unroll
                    for (int ni = 0; ni < 4; ni++)
                        mma_f16(acc[mi][ni], ah[mi], bh[ni]);
            }
        }
        __syncthreads();
        st ^= 1;
    }
#undef GU_LDG
#undef GU_STS

    // epilogue: h = silu(g)*u -> fp16 (pad rows compute exact zeros, written)
    int er = lane >> 2, ec = (lane & 3) * 2;
#pragma unroll
    for (int mi = 0; mi < 2; mi++) {
#pragma unroll
        for (int half = 0; half < 2; half++) {
            size_t row = hrow0 + m0 + wm + mi * 16 + er + half * 8;
#pragma unroll
            for (int ni = 0; ni < 4; ni++) {
                int c = n0 + wn + ni * 8 + ec;
                float g0 = accg[mi][ni][half*2],     u0 = accu[mi][ni][half*2];
                float g1 = accg[mi][ni][half*2 + 1], u1 = accu[mi][ni][half*2 + 1];
                float f0 = (g0 / (1.f + __expf(-g0))) * u0;
                float f1 = (g1 / (1.f + __expf(-g1))) * u1;
                *(uint32_t*)(oh + row * ID + c) =
                    pack2(__float2half_rn(f0), __float2half_rn(f1));
            }
        }
    }
}

// ============================================================================
// GEMM2 fused (single launch): tiles over permuted rows of expert z.
// Two sequential K-phases into ONE accumulator:
//   ph0: acc += hs[perm[p]] @ Ws_down    (gathered A)
//   ph1: acc += hr[p]       @ We_down[z] (contiguous A)
// Then out[perm[p]] = acc, written exactly once (TOP_K=1 covers all tokens).
// ============================================================================
__global__ __launch_bounds__(256)
void down_kernel(const float* __restrict__ Wds, const float* __restrict__ Wde,
                 float* __restrict__ out) {
    extern __shared__ char smem[];
    __shared__ int s_tok[128];

    int tid = threadIdx.x, wid = tid >> 5, lane = tid & 31;
    int e = blockIdx.z;
    int obase = g_offsets[e], cnt = g_offsets[e + 1] - obase;
    int m0 = blockIdx.x * 128;
    if (m0 >= cnt) return;
    int n0 = blockIdx.y * 64;

    if (tid < 128) {
        int gr = m0 + tid;
        s_tok[tid] = (gr < cnt) ? g_perm[obase + gr] : 0;
    }
    __syncthreads();

    int sa_row = tid >> 1, sa_col = (tid & 1) * 16;
    const __half* pAs = g_hs + (size_t)s_tok[sa_row] * ID + sa_col;
    const __half* pAr = g_hr + (size_t)(e * 1024 + m0 + sa_row) * ID + sa_col;
    int sb_k = tid >> 3, sb_j = (tid & 7) * 8;
    const float* pWs = Wds + (size_t)sb_k * HD + n0 + sb_j;
    const float* pWe = Wde + (size_t)e * ID * HD + (size_t)sb_k * HD + n0 + sb_j;
    int a_boff = (sa_row * APITCH + sa_col) * 2;
    int b_boff = (sb_k * BPITCH + sb_j) * 2;

    int wm = (wid >> 1) * 32, wn = (wid & 1) * 32;
    uint32_t sbase = smem_u32(smem);
    int a_lr = lane & 15, a_lc = (lane >> 4) * 8;
    int b_lk = (lane & 7) + (lane >> 4) * 8, b_ln = ((lane >> 3) & 1) * 8;

    float acc[2][4][4] = {};

    uint4 a_c0, a_c1, b_c;
#define DN_LDG(it) { \
    const __half* ph = pA + (it) * 32; \
    a_c0 = *(const uint4*)ph; a_c1 = *(const uint4*)(ph + 8); \
    const float* pw = pW + (size_t)(it) * 32 * HD; \
    b_c = cvtpack8(*(const float4*)pw, *(const float4*)(pw + 4), 1.f); }
#define DN_STS(st) { \
    char* base = smem + (st) * DN_SS; \
    *(uint4*)(base + DN_A + a_boff) = a_c0; \
    *(uint4*)(base + DN_A + a_boff + 16) = a_c1; \
    *(uint4*)(base + DN_B + b_boff) = b_c; }

#pragma unroll 1
    for (int ph2 = 0; ph2 < 2; ph2++) {
        const __half* pA = ph2 ? pAr : pAs;
        const float* pW = ph2 ? pWe : pWs;

        DN_LDG(0);
        DN_STS(0);
        DN_LDG(1);
        __syncthreads();

        int st = 0;
        for (int it = 0; it < NK2; it++) {
            if (it + 1 < NK2) {
                DN_STS(st ^ 1);
                if (it + 2 < NK2) DN_LDG(it + 2);
            }
            uint32_t sb = sbase + st * DN_SS;
#pragma unroll
            for (int kk = 0; kk < 32; kk += 16) {
                uint32_t ah[2][4];
#pragma unroll
                for (int mi = 0; mi < 2; mi++) {
                    uint32_t ao = (uint32_t)((wm + mi * 16 + a_lr) * APITCH + kk + a_lc) * 2;
                    ldsm4(ah[mi], sb + DN_A + ao);
                }
                uint32_t bh[4][2], r[4];
#pragma unroll
                for (int g2 = 0; g2 < 2; g2++) {
                    uint32_t bo = (uint32_t)((kk + b_lk) * BPITCH + wn + g2 * 16 + b_ln) * 2;
                    ldsm4t(r, sb + DN_B + bo);
                    bh[2*g2][0] = r[0]; bh[2*g2][1] = r[2];
                    bh[2*g2+1][0] = r[1]; bh[2*g2+1][1] = r[3];
                }
#pragma unroll
                for (int mi = 0; mi < 2; mi++)
#pragma unroll
                    for (int ni = 0; ni < 4; ni++)
                        mma_f16(acc[mi][ni], ah[mi], bh[ni]);
            }
            __syncthreads();
            st ^= 1;
        }
    }
#undef DN_LDG
#undef DN_STS

    // epilogue: single write per token (no RMW)
    int er = lane >> 2, ec = (lane & 3) * 2;
#pragma unroll
    for (int mi = 0; mi < 2; mi++) {
#pragma unroll
        for (int half = 0; half < 2; half++) {
            int lrow = wm + mi * 16 + er + half * 8;
            int gr = m0 + lrow;
            if (gr < cnt) {
                int token = s_tok[lrow];
#pragma unroll
                for (int ni = 0; ni < 4; ni++) {
                    int c = n0 + wn + ni * 8 + ec;
                    *(float2*)(out + (size_t)token * HD + c) =
                        make_float2(acc[mi][ni][half*2], acc[mi][ni][half*2 + 1]);
                }
            }
        }
    }
}

// ============================================================================
extern "C" void kernel_launch(void* const* d_in, const int* in_sizes, int n_in,
                              void* d_out, int out_size) {
    const float* x        = (const float*)d_in[0];
    const float* w_router = (const float*)d_in[1];
    const float* ws_gate  = (const float*)d_in[2];
    const float* ws_up    = (const float*)d_in[3];
    const float* ws_down  = (const float*)d_in[4];
    const float* we_gate  = (const float*)d_in[5];
    const float* we_up    = (const float*)d_in[6];
    const float* we_down  = (const float*)d_in[7];
    float* out = (float*)d_out;
    (void)in_sizes; (void)n_in; (void)out_size;

    cudaFuncSetAttribute(gateup_kernel, cudaFuncAttributeMaxDynamicSharedMemorySize, GU_BYTES);
    cudaFuncSetAttribute(down_kernel,   cudaFuncAttributeMaxDynamicSharedMemorySize, DN_BYTES);

    router_kernel<<<T / 8, 256>>>(x, w_router);
    perm_kernel<<<1, T>>>();

    gateup_kernel<<<dim3(T / 128, ID / 64, E + 1), 256, GU_BYTES>>>(
        ws_gate, ws_up, we_gate, we_up, x);

    down_kernel<<<dim3(T / 128, HD / 64, E), 256, DN_BYTES>>>(ws_down, we_down, out);
}

// round 17
// speedup vs baseline: 1.0757x; 1.0757x over previous
#include <cuda_runtime.h>
#include <cuda_fp16.h>
#include <cstdint>

#define T  1024
#define HD 2048
#define ID 4096
#define E  8

#define APITCH 40   // fp16 elems; 80B row pitch (conflict-free for ldmatrix)
#define BPITCH 72   // fp16 elems; 144B row pitch
#define NK1 (HD / 32)
#define NK2 (ID / 32)
#define B_SZ (32 * BPITCH * 2)   // 4608 bytes per B buffer

// ---- scratch ----
__device__ __half g_hs[(size_t)T * ID];
__device__ __half g_hr[(size_t)E * 1024 * ID];
__device__ int   g_expert[T];
__device__ float g_score[T];
__device__ int   g_perm[T];
__device__ int   g_offsets[E + 1];

// ---- helpers ----
__device__ __forceinline__ uint32_t smem_u32(const void* p) {
    uint32_t a;
    asm("{ .reg .u64 t; cvta.to.shared.u64 t, %1; cvt.u32.u64 %0, t; }" : "=r"(a) : "l"(p));
    return a;
}
__device__ __forceinline__ void ldsm4(uint32_t* r, uint32_t a) {
    asm volatile("ldmatrix.sync.aligned.m8n8.x4.shared.b16 {%0,%1,%2,%3}, [%4];"
                 : "=r"(r[0]), "=r"(r[1]), "=r"(r[2]), "=r"(r[3]) : "r"(a));
}
__device__ __forceinline__ void ldsm4t(uint32_t* r, uint32_t a) {
    asm volatile("ldmatrix.sync.aligned.m8n8.x4.trans.shared.b16 {%0,%1,%2,%3}, [%4];"
                 : "=r"(r[0]), "=r"(r[1]), "=r"(r[2]), "=r"(r[3]) : "r"(a));
}
__device__ __forceinline__ void mma_f16(float* c, const uint32_t* a, const uint32_t* b) {
    asm volatile("mma.sync.aligned.m16n8k16.row.col.f32.f16.f16.f32 "
                 "{%0,%1,%2,%3}, {%4,%5,%6,%7}, {%8,%9}, {%0,%1,%2,%3};"
                 : "+f"(c[0]), "+f"(c[1]), "+f"(c[2]), "+f"(c[3])
                 : "r"(a[0]), "r"(a[1]), "r"(a[2]), "r"(a[3]), "r"(b[0]), "r"(b[1]));
}
__device__ __forceinline__ uint32_t pack2(__half a, __half b) {
    __half2 t = __halves2half2(a, b);
    return *(uint32_t*)&t;
}
__device__ __forceinline__ uint4 cvtpack8(float4 v0, float4 v1, float sc) {
    return make_uint4(
        pack2(__float2half_rn(v0.x * sc), __float2half_rn(v0.y * sc)),
        pack2(__float2half_rn(v0.z * sc), __float2half_rn(v0.w * sc)),
        pack2(__float2half_rn(v1.x * sc), __float2half_rn(v1.y * sc)),
        pack2(__float2half_rn(v1.z * sc), __float2half_rn(v1.w * sc)));
}

// ============================================================================
__global__ void router_kernel(const float* __restrict__ x, const float* __restrict__ wr) {
    int warp = (blockIdx.x * blockDim.x + threadIdx.x) >> 5;
    int lane = threadIdx.x & 31;
    if (warp >= T) return;
    const float* xr = x + (size_t)warp * HD;
    float acc[E];
#pragma unroll
    for (int e = 0; e < E; e++) acc[e] = 0.f;
    for (int h = lane; h < HD; h += 32) {
        float xv = xr[h];
        const float* w = wr + (size_t)h * E;
#pragma unroll
        for (int e = 0; e < E; e++) acc[e] += xv * w[e];
    }
#pragma unroll
    for (int e = 0; e < E; e++) {
#pragma unroll
        for (int o = 16; o; o >>= 1) acc[e] += __shfl_xor_sync(0xffffffffu, acc[e], o);
    }
    if (lane == 0) {
        int best = 0; float bv = acc[0];
#pragma unroll
        for (int e = 1; e < E; e++) if (acc[e] > bv) { bv = acc[e]; best = e; }
        g_expert[warp] = best;
        g_score[warp]  = 1.f / (1.f + __expf(-bv));
    }
}

__global__ void perm_kernel() {
    __shared__ int cnt[E], off[E + 1], cur[E];
    int t = threadIdx.x;
    if (t < E) cnt[t] = 0;
    __syncthreads();
    int e = g_expert[t];
    atomicAdd(&cnt[e], 1);
    __syncthreads();
    if (t == 0) {
        off[0] = 0;
        for (int i = 0; i < E; i++) off[i + 1] = off[i] + cnt[i];
    }
    __syncthreads();
    if (t < E) cur[t] = off[t];
    __syncthreads();
    int pos = atomicAdd(&cur[e], 1);
    g_perm[pos] = t;
    if (t <= E) g_offsets[t] = off[t];
}

// ============================================================================
// GEMM1: h = silu(A@Wg)*(A@Wu); A = sc * x[tok], fp32->fp16 in staging.
// BM templated: 128 shared (warps 4m x 2n, tile 32x32),
//               64 routed (warps 2m x 4n, tile 32x16) — cuts pad waste.
// ============================================================================
template<int BM, bool ROUTED>
__global__ __launch_bounds__(256)
void gateup_kernel(const float* __restrict__ Wg0, const float* __restrict__ Wu0,
                   const float* __restrict__ X) {
    constexpr int TPR = 256 / BM;      // threads per A row
    constexpr int CPT = 32 / TPR;      // fp32 cols per thread
    constexpr int NV  = CPT / 8;       // uint4 staging regs (2 or 1)
    constexpr int WN  = (BM == 128) ? 2 : 4;
    constexpr int NI  = 8 / WN;        // 8-col groups per warp (4 or 2)
    constexpr int A_SZ = BM * APITCH * 2;
    constexpr int SS   = A_SZ + 2 * B_SZ;

    extern __shared__ char smem[];
    __shared__ int   s_tok[BM];
    __shared__ float s_scl[BM];

    int tid = threadIdx.x, wid = tid >> 5, lane = tid & 31;

    int cnt, obase; size_t hrow0;
    const float *wg, *wu;
    __half* oh;
    if (ROUTED) {
        int e = blockIdx.z;
        obase = g_offsets[e]; cnt = g_offsets[e + 1] - obase;
        wg = Wg0 + (size_t)e * HD * ID; wu = Wu0 + (size_t)e * HD * ID;
        oh = g_hr; hrow0 = (size_t)e * 1024;
    } else {
        obase = 0; cnt = T; wg = Wg0; wu = Wu0;
        oh = g_hs; hrow0 = 0;
    }
    int m0 = blockIdx.x * BM;
    if (m0 >= cnt) return;
    int n0 = blockIdx.y * 64;

    if (tid < BM) {
        int gr = m0 + tid;
        int tok = 0; float sc = 0.f;
        if (gr < cnt) {
            if (ROUTED) { tok = g_perm[obase + gr]; sc = g_score[tok]; }
            else        { tok = gr;                 sc = 1.f; }
        }
        s_tok[tid] = tok; s_scl[tid] = sc;
    }
    __syncthreads();

    int sa_row = tid / TPR, sa_col = (tid % TPR) * CPT;
    float a_sc = s_scl[sa_row];
    const float* pX = X + (size_t)s_tok[sa_row] * HD + sa_col;
    int sb_k = tid >> 3, sb_j = (tid & 7) * 8;
    const float* pG = wg + (size_t)sb_k * ID + n0 + sb_j;
    const float* pU = wu + (size_t)sb_k * ID + n0 + sb_j;
    int a_boff = (sa_row * APITCH + sa_col) * 2;
    int b_boff = (sb_k * BPITCH + sb_j) * 2;

    int wm = (wid / WN) * 32, wn = (wid % WN) * (NI * 8);
    uint32_t sbase = smem_u32(smem);
    int a_lr = lane & 15, a_lc = (lane >> 4) * 8;
    int b_lk = (lane & 7) + (lane >> 4) * 8, b_ln = ((lane >> 3) & 1) * 8;

    float accg[2][NI][4] = {}, accu[2][NI][4] = {};

    uint4 a_c[NV], b_g, b_u;
    auto LDG = [&](int it) {
#pragma unroll
        for (int j = 0; j < NV; j++) {
            const float* px = pX + it * 32 + j * 8;
            a_c[j] = cvtpack8(*(const float4*)px, *(const float4*)(px + 4), a_sc);
        }
        const float* pg = pG + (size_t)it * 32 * ID;
        b_g = cvtpack8(*(const float4*)pg, *(const float4*)(pg + 4), 1.f);
        const float* pu = pU + (size_t)it * 32 * ID;
        b_u = cvtpack8(*(const float4*)pu, *(const float4*)(pu + 4), 1.f);
    };
    auto STS = [&](int st) {
        char* base = smem + st * SS;
#pragma unroll
        for (int j = 0; j < NV; j++)
            *(uint4*)(base + a_boff + j * 16) = a_c[j];
        *(uint4*)(base + A_SZ + b_boff) = b_g;
        *(uint4*)(base + A_SZ + B_SZ + b_boff) = b_u;
    };

    LDG(0);
    STS(0);
    LDG(1);
    __syncthreads();

    int st = 0;
    for (int it = 0; it < NK1; it++) {
        if (it + 1 < NK1) {
            STS(st ^ 1);
            if (it + 2 < NK1) LDG(it + 2);
        }
        uint32_t sb = sbase + st * SS;
#pragma unroll
        for (int kk = 0; kk < 32; kk += 16) {
            uint32_t ah[2][4];
#pragma unroll
            for (int mi = 0; mi < 2; mi++) {
                uint32_t ao = (uint32_t)((wm + mi * 16 + a_lr) * APITCH + kk + a_lc) * 2;
                ldsm4(ah[mi], sb + ao);
            }
#pragma unroll
            for (int mat = 0; mat < 2; mat++) {
                uint32_t bh[NI][2], r[4];
#pragma unroll
                for (int g2 = 0; g2 < NI / 2; g2++) {
                    uint32_t bo = (uint32_t)((kk + b_lk) * BPITCH + wn + g2 * 16 + b_ln) * 2
                                + A_SZ + (mat ? B_SZ : 0);
                    ldsm4t(r, sb + bo);
                    bh[2*g2][0] = r[0]; bh[2*g2][1] = r[2];
                    bh[2*g2+1][0] = r[1]; bh[2*g2+1][1] = r[3];
                }
                float (*acc)[NI][4] = mat ? accu : accg;
#pragma unroll
                for (int mi = 0; mi < 2; mi++)
#pragma unroll
                    for (int ni = 0; ni < NI; ni++)
                        mma_f16(acc[mi][ni], ah[mi], bh[ni]);
            }
        }
        __syncthreads();
        st ^= 1;
    }

    // epilogue: h = silu(g)*u -> fp16 (pad rows compute exact zeros, written)
    int er = lane >> 2, ec = (lane & 3) * 2;
#pragma unroll
    for (int mi = 0; mi < 2; mi++) {
#pragma unroll
        for (int half = 0; half < 2; half++) {
            size_t row = hrow0 + m0 + wm + mi * 16 + er + half * 8;
#pragma unroll
            for (int ni = 0; ni < NI; ni++) {
                int c = n0 + wn + ni * 8 + ec;
                float g0 = accg[mi][ni][half*2],     u0 = accu[mi][ni][half*2];
                float g1 = accg[mi][ni][half*2 + 1], u1 = accu[mi][ni][half*2 + 1];
                float f0 = (g0 / (1.f + __expf(-g0))) * u0;
                float f1 = (g1 / (1.f + __expf(-g1))) * u1;
                *(uint32_t*)(oh + row * ID + c) =
                    pack2(__float2half_rn(f0), __float2half_rn(f1));
            }
        }
    }
}

// ============================================================================
// GEMM2: down projection. BM=128 shared (writes out), BM=64 routed (RMW).
// ============================================================================
template<int BM, bool ROUTED>
__global__ __launch_bounds__(256)
void down_kernel(const float* __restrict__ Wd0, float* __restrict__ out) {
    constexpr int TPR = 256 / BM;
    constexpr int CPT = 32 / TPR;          // fp16 cols per thread here = CPT
    constexpr int NV  = CPT / 8;
    constexpr int WN  = (BM == 128) ? 2 : 4;
    constexpr int NI  = 8 / WN;
    constexpr int A_SZ = BM * APITCH * 2;
    constexpr int SS   = A_SZ + B_SZ;

    extern __shared__ char smem[];
    __shared__ int s_tok[BM];

    int tid = threadIdx.x, wid = tid >> 5, lane = tid & 31;

    int cnt, obase; size_t arow0;
    const float* wd;
    const __half* ax;
    if (ROUTED) {
        int e = blockIdx.z;
        obase = g_offsets[e]; cnt = g_offsets[e + 1] - obase;
        wd = Wd0 + (size_t)e * ID * HD;
        ax = g_hr; arow0 = (size_t)e * 1024;
    } else {
        obase = 0; cnt = T; wd = Wd0;
        ax = g_hs; arow0 = 0;
    }
    int m0 = blockIdx.x * BM;
    if (m0 >= cnt) return;
    int n0 = blockIdx.y * 64;

    if (ROUTED && tid < BM) {
        int gr = m0 + tid;
        s_tok[tid] = (gr < cnt) ? g_perm[obase + gr] : 0;
    }
    __syncthreads();

    int sa_row = tid / TPR, sa_col = (tid % TPR) * CPT;
    const __half* pA = ax + (arow0 + m0 + sa_row) * ID + sa_col;
    int sb_k = tid >> 3, sb_j = (tid & 7) * 8;
    const float* pW = wd + (size_t)sb_k * HD + n0 + sb_j;
    int a_boff = (sa_row * APITCH + sa_col) * 2;
    int b_boff = (sb_k * BPITCH + sb_j) * 2;

    int wm = (wid / WN) * 32, wn = (wid % WN) * (NI * 8);
    uint32_t sbase = smem_u32(smem);
    int a_lr = lane & 15, a_lc = (lane >> 4) * 8;
    int b_lk = (lane & 7) + (lane >> 4) * 8, b_ln = ((lane >> 3) & 1) * 8;

    float acc[2][NI][4] = {};

    uint4 a_c[NV], b_c;
    auto LDG = [&](int it) {
#pragma unroll
        for (int j = 0; j < NV; j++)
            a_c[j] = *(const uint4*)(pA + it * 32 + j * 8);
        const float* pw = pW + (size_t)it * 32 * HD;
        b_c = cvtpack8(*(const float4*)pw, *(const float4*)(pw + 4), 1.f);
    };
    auto STS = [&](int st) {
        char* base = smem + st * SS;
#pragma unroll
        for (int j = 0; j < NV; j++)
            *(uint4*)(base + a_boff + j * 16) = a_c[j];
        *(uint4*)(base + A_SZ + b_boff) = b_c;
    };

    LDG(0);
    STS(0);
    LDG(1);
    __syncthreads();

    int st = 0;
    for (int it = 0; it < NK2; it++) {
        if (it + 1 < NK2) {
            STS(st ^ 1);
            if (it + 2 < NK2) LDG(it + 2);
        }
        uint32_t sb = sbase + st * SS;
#pragma unroll
        for (int kk = 0; kk < 32; kk += 16) {
            uint32_t ah[2][4];
#pragma unroll
            for (int mi = 0; mi < 2; mi++) {
                uint32_t ao = (uint32_t)((wm + mi * 16 + a_lr) * APITCH + kk + a_lc) * 2;
                ldsm4(ah[mi], sb + ao);
            }
            uint32_t bh[NI][2], r[4];
#pragma unroll
            for (int g2 = 0; g2 < NI / 2; g2++) {
                uint32_t bo = (uint32_t)((kk + b_lk) * BPITCH + wn + g2 * 16 + b_ln) * 2 + A_SZ;
                ldsm4t(r, sb + bo);
                bh[2*g2][0] = r[0]; bh[2*g2][1] = r[2];
                bh[2*g2+1][0] = r[1]; bh[2*g2+1][1] = r[3];
            }
#pragma unroll
            for (int mi = 0; mi < 2; mi++)
#pragma unroll
                for (int ni = 0; ni < NI; ni++)
                    mma_f16(acc[mi][ni], ah[mi], bh[ni]);
        }
        __syncthreads();
        st ^= 1;
    }

    // epilogue: shared writes out[token]; routed RMW (runs after shared pass)
    int er = lane >> 2, ec = (lane & 3) * 2;
#pragma unroll
    for (int mi = 0; mi < 2; mi++) {
#pragma unroll
        for (int half = 0; half < 2; half++) {
            int lrow = wm + mi * 16 + er + half * 8;
            int gr = m0 + lrow;
            if (gr < cnt) {
                int token = ROUTED ? s_tok[lrow] : gr;
#pragma unroll
                for (int ni = 0; ni < NI; ni++) {
                    int c = n0 + wn + ni * 8 + ec;
                    float2 v = make_float2(acc[mi][ni][half*2], acc[mi][ni][half*2 + 1]);
                    float2* p = (float2*)(out + (size_t)token * HD + c);
                    if (ROUTED) { float2 o = *p; v.x += o.x; v.y += o.y; }
                    *p = v;
                }
            }
        }
    }
}

// ============================================================================
extern "C" void kernel_launch(void* const* d_in, const int* in_sizes, int n_in,
                              void* d_out, int out_size) {
    const float* x        = (const float*)d_in[0];
    const float* w_router = (const float*)d_in[1];
    const float* ws_gate  = (const float*)d_in[2];
    const float* ws_up    = (const float*)d_in[3];
    const float* ws_down  = (const float*)d_in[4];
    const float* we_gate  = (const float*)d_in[5];
    const float* we_up    = (const float*)d_in[6];
    const float* we_down  = (const float*)d_in[7];
    float* out = (float*)d_out;
    (void)in_sizes; (void)n_in; (void)out_size;

    constexpr int GU128_SMEM = 2 * (128 * APITCH * 2 + 2 * B_SZ);  // 38912
    constexpr int GU64_SMEM  = 2 * (64 * APITCH * 2 + 2 * B_SZ);   // 28672
    constexpr int DN128_SMEM = 2 * (128 * APITCH * 2 + B_SZ);      // 29696
    constexpr int DN64_SMEM  = 2 * (64 * APITCH * 2 + B_SZ);       // 19456

    cudaFuncSetAttribute(gateup_kernel<128, false>, cudaFuncAttributeMaxDynamicSharedMemorySize, GU128_SMEM);
    cudaFuncSetAttribute(gateup_kernel<64, true>,   cudaFuncAttributeMaxDynamicSharedMemorySize, GU64_SMEM);
    cudaFuncSetAttribute(down_kernel<128, false>,   cudaFuncAttributeMaxDynamicSharedMemorySize, DN128_SMEM);
    cudaFuncSetAttribute(down_kernel<64, true>,     cudaFuncAttributeMaxDynamicSharedMemorySize, DN64_SMEM);

    router_kernel<<<T / 8, 256>>>(x, w_router);
    perm_kernel<<<1, T>>>();

    gateup_kernel<128, false><<<dim3(T / 128, ID / 64, 1), 256, GU128_SMEM>>>(ws_gate, ws_up, x);
    gateup_kernel<64, true><<<dim3(T / 64, ID / 64, E), 256, GU64_SMEM>>>(we_gate, we_up, x);

    down_kernel<128, false><<<dim3(T / 128, HD / 64, 1), 256, DN128_SMEM>>>(ws_down, out);
    down_kernel<64, true><<<dim3(T / 64, HD / 64, E), 256, DN64_SMEM>>>(we_down, out);
}